// round 11
// baseline (speedup 1.0000x reference)
#include <cuda_runtime.h>

#define NT 256
#define TS 64           // tile size (i and j)

__device__ double       g_sum;
__device__ double       g_adj;
__device__ unsigned int g_cnt;

static __device__ __forceinline__ float sqa(float x) {
    float y; asm("sqrt.approx.f32 %0,%1;" : "=f"(y) : "f"(x)); return y;
}

// ---------------- symmetric tile-pair kernel (N % 64 == 0) ----------------
__global__ void __launch_bounds__(NT, 2)
pair_kernel(const float* __restrict__ preds,
            const float* __restrict__ targets,
            const float* __restrict__ adj,
            float* __restrict__ out,
            int N)
{
    const int b = blockIdx.y;
    const int ntile = N / TS;

    // decode pair index -> (I, J), I <= J
    int idx = blockIdx.x;
    int I = 0, rem = ntile;
    while (idx >= rem) { idx -= rem; I++; rem--; }
    const int J = I + idx;

    __shared__ float s_pts[8][2 * TS];      // [px,py,pz,pw,tx,ty,tz,tw][tileI | tileJ]
    __shared__ float d2s[TS][TS + 1];       // stride 65; SCALAR access only (16B-misaligned for odd rows)

    const int tid = threadIdx.x;

    // Stage 64 I-points and 64 J-points (+ squared norms)
    if (tid < 2 * TS) {
        int g = (tid < TS) ? (I * TS + tid) : (J * TS + tid - TS);
        const float* pb = preds   + ((size_t)b * N + g) * 3;
        const float* tb = targets + ((size_t)b * N + g) * 3;
        float x = pb[0], y = pb[1], z = pb[2];
        s_pts[0][tid] = x; s_pts[1][tid] = y; s_pts[2][tid] = z;
        s_pts[3][tid] = fmaf(x, x, fmaf(y, y, z * z));
        float u = tb[0], v = tb[1], w = tb[2];
        s_pts[4][tid] = u; s_pts[5][tid] = v; s_pts[6][tid] = w;
        s_pts[7][tid] = fmaf(u, u, fmaf(v, v, w * w));
    }
    __syncthreads();

    const int jx = tid & 15;    // j-group: cols jx*4 .. jx*4+3 (tile J)
    const int iy = tid >> 4;    // i-group: rows iy*4 .. iy*4+3 (tile I)

    // i-row constants (pre-scaled by -2) from tile-I region [0,64)
    float4 P[4], T[4];
    #pragma unroll
    for (int r = 0; r < 4; r++) {
        int k = iy * 4 + r;
        P[r] = make_float4(-2.f*s_pts[0][k], -2.f*s_pts[1][k], -2.f*s_pts[2][k], s_pts[3][k]);
        T[r] = make_float4(-2.f*s_pts[4][k], -2.f*s_pts[5][k], -2.f*s_pts[6][k], s_pts[7][k]);
    }
    // j points (4 consecutive) from tile-J region [64,128): 16B-aligned (row stride 128 floats)
    const int jc = TS + jx * 4;
    float4 jpx = *(const float4*)&s_pts[0][jc];
    float4 jpy = *(const float4*)&s_pts[1][jc];
    float4 jpz = *(const float4*)&s_pts[2][jc];
    float4 jpw = *(const float4*)&s_pts[3][jc];
    float4 jtx = *(const float4*)&s_pts[4][jc];
    float4 jty = *(const float4*)&s_pts[5][jc];
    float4 jtz = *(const float4*)&s_pts[6][jc];
    float4 jtw = *(const float4*)&s_pts[7][jc];
    const float px_[4] = {jpx.x, jpx.y, jpx.z, jpx.w};
    const float py_[4] = {jpy.x, jpy.y, jpy.z, jpy.w};
    const float pz_[4] = {jpz.x, jpz.y, jpz.z, jpz.w};
    const float pw_[4] = {jpw.x, jpw.y, jpw.z, jpw.w};
    const float tx_[4] = {jtx.x, jtx.y, jtx.z, jtx.w};
    const float ty_[4] = {jty.x, jty.y, jty.z, jty.w};
    const float tz_[4] = {jtz.x, jtz.y, jtz.z, jtz.w};
    const float tw_[4] = {jtw.x, jtw.y, jtw.z, jtw.w};

    float acc = 0.f, accA = 0.f;
    const float* adjB = adj + (size_t)b * N * N;

    // Phase 2+3a: compute d2 once, apply to adj[I,J] (coalesced), stash d2 in SMEM (scalar STS)
    #pragma unroll
    for (int r = 0; r < 4; r++) {
        float d[4];
        #pragma unroll
        for (int q = 0; q < 4; q++) {
            float sqp = fmaf(P[r].x, px_[q], fmaf(P[r].y, py_[q], fmaf(P[r].z, pz_[q], P[r].w + pw_[q])));
            float sqt = fmaf(T[r].x, tx_[q], fmaf(T[r].y, ty_[q], fmaf(T[r].z, tz_[q], T[r].w + tw_[q])));
            float rt  = sqa(fmaxf(sqp * sqt, 0.f));
            d[q] = fmaf(-2.f, rt, sqp + sqt);      // (dp - dt)^2
        }
        float4 a = *(const float4*)&adjB[(size_t)(I * TS + iy * 4 + r) * N + J * TS + jx * 4];
        acc  = fmaf(d[0], a.x, fmaf(d[1], a.y, fmaf(d[2], a.z, fmaf(d[3], a.w, acc))));
        accA += (a.x + a.y) + (a.z + a.w);
        #pragma unroll
        for (int q = 0; q < 4; q++) d2s[iy * 4 + r][jx * 4 + q] = d[q];
    }

    // Phase 3b: off-diagonal pairs also apply d2^T to adj[J,I] (coalesced)
    if (I != J) {
        __syncthreads();
        #pragma unroll
        for (int r = 0; r < 4; r++) {     // rows j' = iy*4+r of the JI block
            float4 aJ = *(const float4*)&adjB[(size_t)(J * TS + iy * 4 + r) * N + I * TS + jx * 4];
            // d2^T[j'][i] = d2s[i-col = jx*4+q][j'-row = iy*4+r], scalar LDS (<=2-way conflict)
            float d0 = d2s[jx * 4 + 0][iy * 4 + r];
            float d1 = d2s[jx * 4 + 1][iy * 4 + r];
            float d2v = d2s[jx * 4 + 2][iy * 4 + r];
            float d3 = d2s[jx * 4 + 3][iy * 4 + r];
            acc  = fmaf(d0, aJ.x, fmaf(d1, aJ.y, fmaf(d2v, aJ.z, fmaf(d3, aJ.w, acc))));
            accA += (aJ.x + aJ.y) + (aJ.z + aJ.w);
        }
    }

    // reduce + single-launch finalize
    #pragma unroll
    for (int off = 16; off > 0; off >>= 1) {
        acc  += __shfl_down_sync(0xffffffffu, acc,  off);
        accA += __shfl_down_sync(0xffffffffu, accA, off);
    }
    __shared__ float2 wsum[NT / 32];
    int wid = tid >> 5, lane = tid & 31;
    if (lane == 0) wsum[wid] = make_float2(acc, accA);
    __syncthreads();
    if (wid == 0) {
        float2 v = (lane < NT / 32) ? wsum[lane] : make_float2(0.f, 0.f);
        #pragma unroll
        for (int off = 4; off > 0; off >>= 1) {
            v.x += __shfl_down_sync(0xffffffffu, v.x, off);
            v.y += __shfl_down_sync(0xffffffffu, v.y, off);
        }
        if (lane == 0) {
            atomicAdd(&g_sum, (double)v.x);
            atomicAdd(&g_adj, (double)v.y);
            __threadfence();
            unsigned int nb  = gridDim.x * gridDim.y;
            unsigned int old = atomicAdd(&g_cnt, 1u);
            if (old % nb == nb - 1u) {
                __threadfence();
                double s = atomicAdd(&g_sum, 0.0);
                double n = atomicAdd(&g_adj, 0.0);
                out[0] = (float)(s / n);
                g_sum = 0.0;
                g_adj = 0.0;
            }
        }
    }
}

// ---------------- generic fallback (any N multiple of 4), R6 structure ----------------
extern __shared__ float s_raw[];

__global__ void __launch_bounds__(NT, 2)
loss_generic(const float* __restrict__ preds,
             const float* __restrict__ targets,
             const float* __restrict__ adj,
             float* __restrict__ out,
             int N)
{
    const int b    = blockIdx.y;
    const int row0 = blockIdx.x * 16;
    float* spx = s_raw;        float* spy = spx + N;
    float* spz = spy + N;      float* spw = spz + N;
    float* stx = spw + N;      float* sty = stx + N;
    float* stz = sty + N;      float* stw = stz + N;
    {
        const float* pb = preds   + (size_t)b * N * 3;
        const float* tb = targets + (size_t)b * N * 3;
        for (int k = threadIdx.x; k < N; k += NT) {
            float x = pb[3*k], y = pb[3*k+1], z = pb[3*k+2];
            spx[k] = x; spy[k] = y; spz[k] = z; spw[k] = fmaf(x, x, fmaf(y, y, z*z));
            float u = tb[3*k], v = tb[3*k+1], w = tb[3*k+2];
            stx[k] = u; sty[k] = v; stz[k] = w; stw[k] = fmaf(u, u, fmaf(v, v, w*w));
        }
    }
    __syncthreads();
    float acc = 0.f, accA = 0.f;
    const int N4 = N >> 2;
    const float* adjB = adj + (size_t)b * N * N;
    for (int ig = 0; ig < 16; ig += 4) {
        const int rbase = row0 + ig;
        float4 P[4], T[4];
        #pragma unroll
        for (int r = 0; r < 4; r++) {
            int k = rbase + r;
            P[r] = make_float4(-2.f*spx[k], -2.f*spy[k], -2.f*spz[k], spw[k]);
            T[r] = make_float4(-2.f*stx[k], -2.f*sty[k], -2.f*stz[k], stw[k]);
        }
        const float4* adjR = (const float4*)(adjB + (size_t)rbase * N);
        for (int jv = threadIdx.x; jv < N4; jv += NT) {
            float4 jpx = ((const float4*)spx)[jv]; float4 jpy = ((const float4*)spy)[jv];
            float4 jpz = ((const float4*)spz)[jv]; float4 jpw = ((const float4*)spw)[jv];
            float4 jtx = ((const float4*)stx)[jv]; float4 jty = ((const float4*)sty)[jv];
            float4 jtz = ((const float4*)stz)[jv]; float4 jtw = ((const float4*)stw)[jv];
            const float px_[4] = {jpx.x, jpx.y, jpx.z, jpx.w};
            const float py_[4] = {jpy.x, jpy.y, jpy.z, jpy.w};
            const float pz_[4] = {jpz.x, jpz.y, jpz.z, jpz.w};
            const float pw_[4] = {jpw.x, jpw.y, jpw.z, jpw.w};
            const float tx_[4] = {jtx.x, jtx.y, jtx.z, jtx.w};
            const float ty_[4] = {jty.x, jty.y, jty.z, jty.w};
            const float tz_[4] = {jtz.x, jtz.y, jtz.z, jtz.w};
            const float tw_[4] = {jtw.x, jtw.y, jtw.z, jtw.w};
            #pragma unroll
            for (int r = 0; r < 4; r++) {
                float4 a = adjR[(size_t)r * N4 + jv];
                const float av[4] = {a.x, a.y, a.z, a.w};
                #pragma unroll
                for (int q = 0; q < 4; q++) {
                    float sqp = fmaf(P[r].x, px_[q], fmaf(P[r].y, py_[q], fmaf(P[r].z, pz_[q], P[r].w + pw_[q])));
                    float sqt = fmaf(T[r].x, tx_[q], fmaf(T[r].y, ty_[q], fmaf(T[r].z, tz_[q], T[r].w + tw_[q])));
                    float rt = sqa(fmaxf(sqp * sqt, 0.f));
                    acc = fmaf(fmaf(-2.f, rt, sqp + sqt), av[q], acc);
                }
                accA += (av[0] + av[1]) + (av[2] + av[3]);
            }
        }
    }
    #pragma unroll
    for (int off = 16; off > 0; off >>= 1) {
        acc  += __shfl_down_sync(0xffffffffu, acc,  off);
        accA += __shfl_down_sync(0xffffffffu, accA, off);
    }
    __shared__ float2 wsum[NT / 32];
    int wid = threadIdx.x >> 5, lane = threadIdx.x & 31;
    if (lane == 0) wsum[wid] = make_float2(acc, accA);
    __syncthreads();
    if (wid == 0) {
        float2 v = (lane < NT / 32) ? wsum[lane] : make_float2(0.f, 0.f);
        #pragma unroll
        for (int off = 4; off > 0; off >>= 1) {
            v.x += __shfl_down_sync(0xffffffffu, v.x, off);
            v.y += __shfl_down_sync(0xffffffffu, v.y, off);
        }
        if (lane == 0) {
            atomicAdd(&g_sum, (double)v.x);
            atomicAdd(&g_adj, (double)v.y);
            __threadfence();
            unsigned int nb  = gridDim.x * gridDim.y;
            unsigned int old = atomicAdd(&g_cnt, 1u);
            if (old % nb == nb - 1u) {
                __threadfence();
                double s = atomicAdd(&g_sum, 0.0);
                double n = atomicAdd(&g_adj, 0.0);
                out[0] = (float)(s / n);
                g_sum = 0.0; g_adj = 0.0;
            }
        }
    }
}

extern "C" void kernel_launch(void* const* d_in, const int* in_sizes, int n_in,
                              void* d_out, int out_size)
{
    const float* preds   = (const float*)d_in[0];
    const float* targets = (const float*)d_in[1];
    const float* adj     = (const float*)d_in[2];

    long long psz   = in_sizes[0];          // B*N*3
    long long adjsz = in_sizes[2];          // B*N*N
    int N = (int)(3LL * adjsz / psz);       // 2048
    int B = (int)(psz / (3LL * N));         // 8

    if (N % TS == 0) {
        int ntile = N / TS;
        dim3 grid(ntile * (ntile + 1) / 2, B);
        pair_kernel<<<grid, NT>>>(preds, targets, adj, (float*)d_out, N);
    } else {
        size_t smem = (size_t)8 * N * sizeof(float);
        cudaFuncSetAttribute(loss_generic, cudaFuncAttributeMaxDynamicSharedMemorySize, (int)smem);
        dim3 grid(N / 16, B);
        loss_generic<<<grid, NT, smem>>>(preds, targets, adj, (float*)d_out, N);
    }
}

// round 12
// speedup vs baseline: 1.2414x; 1.2414x over previous
#include <cuda_runtime.h>

#define NT 256
#define TS 64           // tile size
#define KP 4            // tile-pairs per CTA

__device__ double       g_sum;
__device__ double       g_adj;
__device__ unsigned int g_cnt;

static __device__ __forceinline__ float sqa(float x) {
    float y; asm("sqrt.approx.f32 %0,%1;" : "=f"(y) : "f"(x)); return y;
}

// ---------------- symmetric multi-pair kernel (N % 64 == 0) ----------------
__global__ void __launch_bounds__(NT, 2)
pair_kernel(const float* __restrict__ preds,
            const float* __restrict__ targets,
            const float* __restrict__ adj,
            float* __restrict__ out,
            int N)
{
    const int b     = blockIdx.y;
    const int ntile = N / TS;
    const int PB    = ntile * (ntile + 1) / 2;      // pairs per batch
    const int p0    = blockIdx.x * KP;

    __shared__ float s_pts[KP][2][8][TS];  // [pair][side I/J][px,py,pz,pw,tx,ty,tz,tw][pt]
    __shared__ float d2s[TS][TS + 1];      // stride 65; SCALAR access only
    __shared__ int   s_IJ[KP][2];

    const int tid = threadIdx.x;

    // ---- decode first pair (closed form + exact fixup), enumerate KP pairs ----
    // cum(I) = I*ntile - I*(I-1)/2 ; find I with cum(I) <= p0 < cum(I+1)
    int I0;
    {
        float nn = 2.f * ntile + 1.f;
        I0 = (int)((nn - sqrtf(fmaxf(nn * nn - 8.f * (float)p0, 0.f))) * 0.5f);
        if (I0 < 0) I0 = 0;
        if (I0 > ntile - 1) I0 = ntile - 1;
        while (I0 + 1 <= ntile - 1 &&
               (I0 + 1) * ntile - ((I0 + 1) * I0) / 2 <= p0) I0++;
        while (I0 > 0 && I0 * ntile - (I0 * (I0 - 1)) / 2 > p0) I0--;
    }
    int Jc = I0 + (p0 - (I0 * ntile - (I0 * (I0 - 1)) / 2));
    int Ic = I0;
    if (tid == 0) {
        int Ii = Ic, Jj = Jc;
        #pragma unroll
        for (int k = 0; k < KP; k++) {
            s_IJ[k][0] = Ii; s_IJ[k][1] = Jj;
            Jj++; if (Jj == ntile) { Ii++; Jj = Ii; }
        }
    }
    __syncthreads();

    // ---- stage points for all KP pairs (one sync for the whole CTA) ----
    for (int s = tid; s < KP * 2 * TS; s += NT) {
        int k    = s >> 7;          // / (2*TS)
        int side = (s >> 6) & 1;
        int idx  = s & (TS - 1);
        if (p0 + k < PB) {
            int g = s_IJ[k][side] * TS + idx;
            const float* pb = preds   + ((size_t)b * N + g) * 3;
            const float* tb = targets + ((size_t)b * N + g) * 3;
            float x = pb[0], y = pb[1], z = pb[2];
            s_pts[k][side][0][idx] = x; s_pts[k][side][1][idx] = y;
            s_pts[k][side][2][idx] = z;
            s_pts[k][side][3][idx] = fmaf(x, x, fmaf(y, y, z * z));
            float u = tb[0], v = tb[1], w = tb[2];
            s_pts[k][side][4][idx] = u; s_pts[k][side][5][idx] = v;
            s_pts[k][side][6][idx] = w;
            s_pts[k][side][7][idx] = fmaf(u, u, fmaf(v, v, w * w));
        }
    }
    __syncthreads();

    const int jx = tid & 15;    // j-group: cols jx*4..+3
    const int iy = tid >> 4;    // i-group: rows iy*4..+3

    float acc = 0.f, accA = 0.f;
    const float* adjB = adj + (size_t)b * N * N;

    int I = Ic, J = Jc;
    #pragma unroll
    for (int k = 0; k < KP; k++) {
        if (p0 + k < PB) {
            // i-row constants (pre-scaled by -2)
            float4 P[4], T[4];
            #pragma unroll
            for (int r = 0; r < 4; r++) {
                int i = iy * 4 + r;
                P[r] = make_float4(-2.f * s_pts[k][0][0][i], -2.f * s_pts[k][0][1][i],
                                   -2.f * s_pts[k][0][2][i],        s_pts[k][0][3][i]);
                T[r] = make_float4(-2.f * s_pts[k][0][4][i], -2.f * s_pts[k][0][5][i],
                                   -2.f * s_pts[k][0][6][i],        s_pts[k][0][7][i]);
            }
            // j-quad (vector LDS; 16B-aligned rows)
            const int jc = jx * 4;
            float4 jpx = *(const float4*)&s_pts[k][1][0][jc];
            float4 jpy = *(const float4*)&s_pts[k][1][1][jc];
            float4 jpz = *(const float4*)&s_pts[k][1][2][jc];
            float4 jpw = *(const float4*)&s_pts[k][1][3][jc];
            float4 jtx = *(const float4*)&s_pts[k][1][4][jc];
            float4 jty = *(const float4*)&s_pts[k][1][5][jc];
            float4 jtz = *(const float4*)&s_pts[k][1][6][jc];
            float4 jtw = *(const float4*)&s_pts[k][1][7][jc];
            const float px_[4] = {jpx.x, jpx.y, jpx.z, jpx.w};
            const float py_[4] = {jpy.x, jpy.y, jpy.z, jpy.w};
            const float pz_[4] = {jpz.x, jpz.y, jpz.z, jpz.w};
            const float pw_[4] = {jpw.x, jpw.y, jpw.z, jpw.w};
            const float tx_[4] = {jtx.x, jtx.y, jtx.z, jtx.w};
            const float ty_[4] = {jty.x, jty.y, jty.z, jty.w};
            const float tz_[4] = {jtz.x, jtz.y, jtz.z, jtz.w};
            const float tw_[4] = {jtw.x, jtw.y, jtw.z, jtw.w};

            // Phase A: d2 once, apply to adj[I,J] (coalesced), stash for transpose
            #pragma unroll
            for (int r = 0; r < 4; r++) {
                float d[4];
                #pragma unroll
                for (int q = 0; q < 4; q++) {
                    float sqp = fmaf(P[r].x, px_[q], fmaf(P[r].y, py_[q], fmaf(P[r].z, pz_[q], P[r].w + pw_[q])));
                    float sqt = fmaf(T[r].x, tx_[q], fmaf(T[r].y, ty_[q], fmaf(T[r].z, tz_[q], T[r].w + tw_[q])));
                    float rt  = sqa(fmaxf(sqp * sqt, 0.f));
                    d[q] = fmaf(-2.f, rt, sqp + sqt);      // (dp - dt)^2
                }
                float4 a = *(const float4*)&adjB[(size_t)(I * TS + iy * 4 + r) * N + J * TS + jx * 4];
                acc  = fmaf(d[0], a.x, fmaf(d[1], a.y, fmaf(d[2], a.z, fmaf(d[3], a.w, acc))));
                accA += (a.x + a.y) + (a.z + a.w);
                #pragma unroll
                for (int q = 0; q < 4; q++) d2s[iy * 4 + r][jx * 4 + q] = d[q];
            }

            __syncthreads();   // d2s writes -> transposed reads

            // Phase B: off-diagonal applies d2^T to adj[J,I] (coalesced)
            if (I != J) {
                #pragma unroll
                for (int r = 0; r < 4; r++) {
                    float4 aJ = *(const float4*)&adjB[(size_t)(J * TS + iy * 4 + r) * N + I * TS + jx * 4];
                    float d0 = d2s[jx * 4 + 0][iy * 4 + r];
                    float d1 = d2s[jx * 4 + 1][iy * 4 + r];
                    float d2v = d2s[jx * 4 + 2][iy * 4 + r];
                    float d3 = d2s[jx * 4 + 3][iy * 4 + r];
                    acc  = fmaf(d0, aJ.x, fmaf(d1, aJ.y, fmaf(d2v, aJ.z, fmaf(d3, aJ.w, acc))));
                    accA += (aJ.x + aJ.y) + (aJ.z + aJ.w);
                }
                __syncthreads();   // transposed reads -> next pair's writes
            }
            // diagonal: the single sync above already orders writes vs next pair
        }
        J++; if (J == ntile) { I++; J = I; }
    }

    // reduce + single-launch finalize
    #pragma unroll
    for (int off = 16; off > 0; off >>= 1) {
        acc  += __shfl_down_sync(0xffffffffu, acc,  off);
        accA += __shfl_down_sync(0xffffffffu, accA, off);
    }
    __shared__ float2 wsum[NT / 32];
    int wid = tid >> 5, lane = tid & 31;
    if (lane == 0) wsum[wid] = make_float2(acc, accA);
    __syncthreads();
    if (wid == 0) {
        float2 v = (lane < NT / 32) ? wsum[lane] : make_float2(0.f, 0.f);
        #pragma unroll
        for (int off = 4; off > 0; off >>= 1) {
            v.x += __shfl_down_sync(0xffffffffu, v.x, off);
            v.y += __shfl_down_sync(0xffffffffu, v.y, off);
        }
        if (lane == 0) {
            atomicAdd(&g_sum, (double)v.x);
            atomicAdd(&g_adj, (double)v.y);
            __threadfence();
            unsigned int nb  = gridDim.x * gridDim.y;
            unsigned int old = atomicAdd(&g_cnt, 1u);
            if (old % nb == nb - 1u) {
                __threadfence();
                double s = atomicAdd(&g_sum, 0.0);
                double n = atomicAdd(&g_adj, 0.0);
                out[0] = (float)(s / n);
                g_sum = 0.0;
                g_adj = 0.0;
            }
        }
    }
}

// ---------------- generic fallback (any N multiple of 4), R6 structure ----------------
extern __shared__ float s_raw[];

__global__ void __launch_bounds__(NT, 2)
loss_generic(const float* __restrict__ preds,
             const float* __restrict__ targets,
             const float* __restrict__ adj,
             float* __restrict__ out,
             int N)
{
    const int b    = blockIdx.y;
    const int row0 = blockIdx.x * 16;
    float* spx = s_raw;        float* spy = spx + N;
    float* spz = spy + N;      float* spw = spz + N;
    float* stx = spw + N;      float* sty = stx + N;
    float* stz = sty + N;      float* stw = stz + N;
    {
        const float* pb = preds   + (size_t)b * N * 3;
        const float* tb = targets + (size_t)b * N * 3;
        for (int k = threadIdx.x; k < N; k += NT) {
            float x = pb[3*k], y = pb[3*k+1], z = pb[3*k+2];
            spx[k] = x; spy[k] = y; spz[k] = z; spw[k] = fmaf(x, x, fmaf(y, y, z*z));
            float u = tb[3*k], v = tb[3*k+1], w = tb[3*k+2];
            stx[k] = u; sty[k] = v; stz[k] = w; stw[k] = fmaf(u, u, fmaf(v, v, w*w));
        }
    }
    __syncthreads();
    float acc = 0.f, accA = 0.f;
    const int N4 = N >> 2;
    const float* adjB = adj + (size_t)b * N * N;
    for (int ig = 0; ig < 16; ig += 4) {
        const int rbase = row0 + ig;
        float4 P[4], T[4];
        #pragma unroll
        for (int r = 0; r < 4; r++) {
            int k = rbase + r;
            P[r] = make_float4(-2.f*spx[k], -2.f*spy[k], -2.f*spz[k], spw[k]);
            T[r] = make_float4(-2.f*stx[k], -2.f*sty[k], -2.f*stz[k], stw[k]);
        }
        const float4* adjR = (const float4*)(adjB + (size_t)rbase * N);
        for (int jv = threadIdx.x; jv < N4; jv += NT) {
            float4 jpx = ((const float4*)spx)[jv]; float4 jpy = ((const float4*)spy)[jv];
            float4 jpz = ((const float4*)spz)[jv]; float4 jpw = ((const float4*)spw)[jv];
            float4 jtx = ((const float4*)stx)[jv]; float4 jty = ((const float4*)sty)[jv];
            float4 jtz = ((const float4*)stz)[jv]; float4 jtw = ((const float4*)stw)[jv];
            const float px_[4] = {jpx.x, jpx.y, jpx.z, jpx.w};
            const float py_[4] = {jpy.x, jpy.y, jpy.z, jpy.w};
            const float pz_[4] = {jpz.x, jpz.y, jpz.z, jpz.w};
            const float pw_[4] = {jpw.x, jpw.y, jpw.z, jpw.w};
            const float tx_[4] = {jtx.x, jtx.y, jtx.z, jtx.w};
            const float ty_[4] = {jty.x, jty.y, jty.z, jty.w};
            const float tz_[4] = {jtz.x, jtz.y, jtz.z, jtz.w};
            const float tw_[4] = {jtw.x, jtw.y, jtw.z, jtw.w};
            #pragma unroll
            for (int r = 0; r < 4; r++) {
                float4 a = adjR[(size_t)r * N4 + jv];
                const float av[4] = {a.x, a.y, a.z, a.w};
                #pragma unroll
                for (int q = 0; q < 4; q++) {
                    float sqp = fmaf(P[r].x, px_[q], fmaf(P[r].y, py_[q], fmaf(P[r].z, pz_[q], P[r].w + pw_[q])));
                    float sqt = fmaf(T[r].x, tx_[q], fmaf(T[r].y, ty_[q], fmaf(T[r].z, tz_[q], T[r].w + tw_[q])));
                    float rt = sqa(fmaxf(sqp * sqt, 0.f));
                    acc = fmaf(fmaf(-2.f, rt, sqp + sqt), av[q], acc);
                }
                accA += (av[0] + av[1]) + (av[2] + av[3]);
            }
        }
    }
    #pragma unroll
    for (int off = 16; off > 0; off >>= 1) {
        acc  += __shfl_down_sync(0xffffffffu, acc,  off);
        accA += __shfl_down_sync(0xffffffffu, accA, off);
    }
    __shared__ float2 wsum[NT / 32];
    int wid = threadIdx.x >> 5, lane = threadIdx.x & 31;
    if (lane == 0) wsum[wid] = make_float2(acc, accA);
    __syncthreads();
    if (wid == 0) {
        float2 v = (lane < NT / 32) ? wsum[lane] : make_float2(0.f, 0.f);
        #pragma unroll
        for (int off = 4; off > 0; off >>= 1) {
            v.x += __shfl_down_sync(0xffffffffu, v.x, off);
            v.y += __shfl_down_sync(0xffffffffu, v.y, off);
        }
        if (lane == 0) {
            atomicAdd(&g_sum, (double)v.x);
            atomicAdd(&g_adj, (double)v.y);
            __threadfence();
            unsigned int nb  = gridDim.x * gridDim.y;
            unsigned int old = atomicAdd(&g_cnt, 1u);
            if (old % nb == nb - 1u) {
                __threadfence();
                double s = atomicAdd(&g_sum, 0.0);
                double n = atomicAdd(&g_adj, 0.0);
                out[0] = (float)(s / n);
                g_sum = 0.0; g_adj = 0.0;
            }
        }
    }
}

extern "C" void kernel_launch(void* const* d_in, const int* in_sizes, int n_in,
                              void* d_out, int out_size)
{
    const float* preds   = (const float*)d_in[0];
    const float* targets = (const float*)d_in[1];
    const float* adj     = (const float*)d_in[2];

    long long psz   = in_sizes[0];          // B*N*3
    long long adjsz = in_sizes[2];          // B*N*N
    int N = (int)(3LL * adjsz / psz);       // 2048
    int B = (int)(psz / (3LL * N));         // 8

    if (N % TS == 0) {
        int ntile = N / TS;
        int PB = ntile * (ntile + 1) / 2;
        dim3 grid((PB + KP - 1) / KP, B);
        pair_kernel<<<grid, NT>>>(preds, targets, adj, (float*)d_out, N);
    } else {
        size_t smem = (size_t)8 * N * sizeof(float);
        cudaFuncSetAttribute(loss_generic, cudaFuncAttributeMaxDynamicSharedMemorySize, (int)smem);
        dim3 grid(N / 16, B);
        loss_generic<<<grid, NT, smem>>>(preds, targets, adj, (float*)d_out, N);
    }
}